// round 8
// baseline (speedup 1.0000x reference)
#include <cuda_runtime.h>
#include <math.h>

#define BB 256
#define TT 512
#define II 128
#define HH 256
#define H2 512
#define H3 768
#define SMS 148
#define GRID 444          // 3 CTAs per SM, classic placement keeps bid%148 on one SM
#define NTHR 128
#define GSTRIDE (GRID * NTHR)

typedef unsigned long long ull;

#define ASP 36            // As row pitch (floats)
#define WSP 68            // Ws row pitch (floats)
#define SA_BUF (32 * ASP)
#define SW_BUF (32 * WSP)

enum { EPI_RAW = 0, EPI_BIAS = 1, EPI_TANH = 2 };

// ---------------- persistent device scratch (no allocations) ----------------
__device__ float g_W1t[H2 * H2];     // transposed weights: Wt[k][n] = W[n][k]
__device__ float g_W2t[H2 * H2];
__device__ float g_W3t[H2 * H2];
__device__ float g_WihT[HH * H3];
__device__ float g_WhhT[HH * H3];
__device__ float g_WcinT[II * HH];

__device__ float g_com[BB][H2];      // [c | c_in_t]
__device__ float g_a1p[2][BB][H2];   // K-split partials
__device__ float g_a2p[2][BB][H2];
__device__ float g_a3p[2][BB][H2];
__device__ float g_gi[BB][H3];
__device__ float g_gh[BB][H3];
__device__ float g_c[BB][HH];
__device__ float g_h[BB][HH];
__device__ float g_n[BB];

__device__ unsigned g_bar_count;
__device__ volatile unsigned g_bar_gen;

__device__ __forceinline__ void grid_sync() {
    __syncthreads();
    if (threadIdx.x == 0) {
        unsigned gen = g_bar_gen;
        __threadfence();
        if (atomicAdd(&g_bar_count, 1u) == GRID - 1) {
            g_bar_count = 0;
            __threadfence();
            g_bar_gen = gen + 1;
        } else {
            while (g_bar_gen == gen) __nanosleep(32);
        }
        __threadfence();
    }
    __syncthreads();
}

__device__ __forceinline__ float sigf(float x) { return 1.f / (1.f + expf(-x)); }

// ---------------- packed f32x2 helpers ----------------
__device__ __forceinline__ ull pack2(float x, float y) {
    ull r; asm("mov.b64 %0,{%1,%2};" : "=l"(r) : "f"(x), "f"(y)); return r;
}
__device__ __forceinline__ void unpack2(ull v, float& x, float& y) {
    asm("mov.b64 {%0,%1},%2;" : "=f"(x), "=f"(y) : "l"(v));
}
__device__ __forceinline__ void fma2(ull& d, ull a, ull b) {
    asm("fma.rn.f32x2 %0, %1, %2, %0;" : "+l"(d) : "l"(a), "l"(b));
}

// -------------------------------------------------------------------------
// One 32x64 output tile of C = epi(A @ Wt), 128 threads, per-thread 2x8.
// (R6-proven shape: per kk = LDS.64 + 2xLDS.128 + 8 FFMA2 -> fma:lsu = 16:10)
// -------------------------------------------------------------------------
template<int EPI, bool COMBINE>
__device__ __noinline__ void gemm32x64(
    const float* __restrict__ A0, const float* __restrict__ A1,
    const float* __restrict__ Ab, int lda, int koff,
    const float* __restrict__ Wt, int ldw,
    const float* __restrict__ bias,
    float* __restrict__ C, int ldc,
    int rowBase, int colBase, int nkt,
    float* __restrict__ As, float* __restrict__ Ws)
{
    const int tid  = threadIdx.x;
    const int tx4  = (tid & 7) * 4;        // col block offset
    const int ty2  = (tid >> 3) * 2;       // row pair
    const int arow = tid >> 3;             // A-stage row (and +16)
    const int akq  = tid & 7;              // A-stage k-quad
    const int wkk  = tid >> 4;             // W-stage kk (0..7, +8,+16,+24)
    const int wc4  = (tid & 15) * 4;       // W-stage col quad

    ull c00 = 0, c01 = 0, c02 = 0, c03 = 0;
    ull c10 = 0, c11 = 0, c12 = 0, c13 = 0;
    float4 va0, va1, vw0, vw1, vw2, vw3;

#define LOAD_T(kt)                                                              \
    {                                                                           \
        int kg = koff + (kt) * 32;                                              \
        const float* ap = A0 + (size_t)(rowBase + arow) * lda + kg + akq * 4;   \
        va0 = *(const float4*)ap;                                               \
        va1 = *(const float4*)(ap + 16 * (size_t)lda);                          \
        if (COMBINE) {                                                          \
            const float* a1p = A1 + (size_t)(rowBase + arow) * lda + kg + akq * 4; \
            float4 u0 = *(const float4*)a1p;                                    \
            float4 u1 = *(const float4*)(a1p + 16 * (size_t)lda);               \
            float4 bb = *(const float4*)(Ab + kg + akq * 4);                    \
            va0.x = fmaxf(va0.x + u0.x + bb.x, 0.f);                            \
            va0.y = fmaxf(va0.y + u0.y + bb.y, 0.f);                            \
            va0.z = fmaxf(va0.z + u0.z + bb.z, 0.f);                            \
            va0.w = fmaxf(va0.w + u0.w + bb.w, 0.f);                            \
            va1.x = fmaxf(va1.x + u1.x + bb.x, 0.f);                            \
            va1.y = fmaxf(va1.y + u1.y + bb.y, 0.f);                            \
            va1.z = fmaxf(va1.z + u1.z + bb.z, 0.f);                            \
            va1.w = fmaxf(va1.w + u1.w + bb.w, 0.f);                            \
        }                                                                       \
        const float* wp = Wt + (size_t)(kg + wkk) * ldw + colBase + wc4;        \
        vw0 = *(const float4*)wp;                                               \
        vw1 = *(const float4*)(wp + 8  * (size_t)ldw);                          \
        vw2 = *(const float4*)(wp + 16 * (size_t)ldw);                          \
        vw3 = *(const float4*)(wp + 24 * (size_t)ldw);                          \
    }

#define STORE_T(bi)                                                             \
    {                                                                           \
        float* as = As + (bi) * SA_BUF;                                         \
        float* ws = Ws + (bi) * SW_BUF;                                         \
        as[(akq * 4 + 0) * ASP + arow]      = va0.x;                            \
        as[(akq * 4 + 1) * ASP + arow]      = va0.y;                            \
        as[(akq * 4 + 2) * ASP + arow]      = va0.z;                            \
        as[(akq * 4 + 3) * ASP + arow]      = va0.w;                            \
        as[(akq * 4 + 0) * ASP + arow + 16] = va1.x;                            \
        as[(akq * 4 + 1) * ASP + arow + 16] = va1.y;                            \
        as[(akq * 4 + 2) * ASP + arow + 16] = va1.z;                            \
        as[(akq * 4 + 3) * ASP + arow + 16] = va1.w;                            \
        *(float4*)(ws + (wkk + 0)  * WSP + wc4) = vw0;                          \
        *(float4*)(ws + (wkk + 8)  * WSP + wc4) = vw1;                          \
        *(float4*)(ws + (wkk + 16) * WSP + wc4) = vw2;                          \
        *(float4*)(ws + (wkk + 24) * WSP + wc4) = vw3;                          \
    }

    LOAD_T(0);
    STORE_T(0);
    __syncthreads();

    for (int kt = 0; kt < nkt; kt++) {
        if (kt + 1 < nkt) LOAD_T(kt + 1);
        {
            const float* as = As + (kt & 1) * SA_BUF;
            const float* ws = Ws + (kt & 1) * SW_BUF;
#pragma unroll
            for (int kk = 0; kk < 32; kk++) {
                ull a01 = *(const ull*)(as + kk * ASP + ty2);
                float a0, a1;
                unpack2(a01, a0, a1);
                ull d0 = pack2(a0, a0);
                ull d1 = pack2(a1, a1);
                ulonglong2 wA = *(const ulonglong2*)(ws + kk * WSP + tx4);
                ulonglong2 wB = *(const ulonglong2*)(ws + kk * WSP + 32 + tx4);
                fma2(c00, d0, wA.x);
                fma2(c01, d0, wA.y);
                fma2(c02, d0, wB.x);
                fma2(c03, d0, wB.y);
                fma2(c10, d1, wA.x);
                fma2(c11, d1, wA.y);
                fma2(c12, d1, wB.x);
                fma2(c13, d1, wB.y);
            }
        }
        if (kt + 1 < nkt) STORE_T((kt + 1) & 1);
        __syncthreads();
    }
#undef LOAD_T
#undef STORE_T

    // epilogue: rows rowBase+ty2, +1; col blocks at tx4 and 32+tx4
    float4 o00, o01, o10, o11;
    unpack2(c00, o00.x, o00.y); unpack2(c01, o00.z, o00.w);
    unpack2(c02, o01.x, o01.y); unpack2(c03, o01.z, o01.w);
    unpack2(c10, o10.x, o10.y); unpack2(c11, o10.z, o10.w);
    unpack2(c12, o11.x, o11.y); unpack2(c13, o11.z, o11.w);
    if (EPI != EPI_RAW) {
        float4 b0 = *(const float4*)(bias + colBase + tx4);
        float4 b1 = *(const float4*)(bias + colBase + 32 + tx4);
        o00.x += b0.x; o00.y += b0.y; o00.z += b0.z; o00.w += b0.w;
        o10.x += b0.x; o10.y += b0.y; o10.z += b0.z; o10.w += b0.w;
        o01.x += b1.x; o01.y += b1.y; o01.z += b1.z; o01.w += b1.w;
        o11.x += b1.x; o11.y += b1.y; o11.z += b1.z; o11.w += b1.w;
        if (EPI == EPI_TANH) {
            o00.x = tanhf(o00.x); o00.y = tanhf(o00.y); o00.z = tanhf(o00.z); o00.w = tanhf(o00.w);
            o01.x = tanhf(o01.x); o01.y = tanhf(o01.y); o01.z = tanhf(o01.z); o01.w = tanhf(o01.w);
            o10.x = tanhf(o10.x); o10.y = tanhf(o10.y); o10.z = tanhf(o10.z); o10.w = tanhf(o10.w);
            o11.x = tanhf(o11.x); o11.y = tanhf(o11.y); o11.z = tanhf(o11.z); o11.w = tanhf(o11.w);
        }
    }
    float* crow0 = C + (size_t)(rowBase + ty2) * ldc + colBase;
    float* crow1 = crow0 + ldc;
    *(float4*)(crow0 + tx4)      = o00;
    *(float4*)(crow0 + 32 + tx4) = o01;
    *(float4*)(crow1 + tx4)      = o10;
    *(float4*)(crow1 + 32 + tx4) = o11;
}

struct P {
    const float *b1, *b2, *b3, *bih, *bhh;
};

__device__ __forceinline__ void do_g(int gq, bool is_gi, const P& p,
                                     float* As, float* Ws)
{
    int rt = gq / 12, ct = gq % 12;
    if (is_gi)
        gemm32x64<EPI_BIAS, false>(&g_c[0][0], 0, 0, HH, 0, g_WihT, H3, p.bih,
                                   &g_gi[0][0], H3, rt * 32, ct * 64, 8, As, Ws);
    else
        gemm32x64<EPI_BIAS, false>(&g_h[0][0], 0, 0, HH, 0, g_WhhT, H3, p.bhh,
                                   &g_gh[0][0], H3, rt * 32, ct * 64, 8, As, Ws);
}

// phases 0..2: 192 jobs (128 a-layer + 64 g); phase 3: 192 g jobs (epilogue)
__device__ void exec_job(int ph, int j, const P& p, float* As, float* Ws)
{
    if (ph < 3 && j < 128) {
        int rt = j >> 4, kh = (j >> 3) & 1, ct = j & 7;
        int rb = rt * 32, cb = ct * 64, ko = kh * 256;
        if (ph == 0)
            gemm32x64<EPI_RAW, false>(&g_com[0][0], 0, 0, H2, ko, g_W1t, H2, 0,
                                      &g_a1p[kh][0][0], H2, rb, cb, 8, As, Ws);
        else if (ph == 1)
            gemm32x64<EPI_RAW, true>(&g_a1p[0][0][0], &g_a1p[1][0][0], p.b1, H2, ko,
                                     g_W2t, H2, 0, &g_a2p[kh][0][0], H2, rb, cb, 8, As, Ws);
        else
            gemm32x64<EPI_RAW, true>(&g_a2p[0][0][0], &g_a2p[1][0][0], p.b2, H2, ko,
                                     g_W3t, H2, 0, &g_a3p[kh][0][0], H2, rb, cb, 8, As, Ws);
    } else if (ph == 3) {
        if (j < 96) do_g(j, true, p, As, Ws);
        else        do_g(j - 96, false, p, As, Ws);
    } else if (ph == 0) {
        do_g(j - 128, true, p, As, Ws);                        // gi 0..63
    } else if (ph == 1) {
        if (j < 160) do_g(64 + (j - 128), true, p, As, Ws);    // gi 64..95
        else         do_g(j - 160, false, p, As, Ws);          // gh 0..31
    } else {
        do_g(32 + (j - 128), false, p, As, Ws);                // gh 32..95
    }
}

// parallel-slot mapping of 192 jobs onto 148 SMs x 3 CTA slots:
// SMs 0..43 run 2 concurrent jobs (slots 0,1), SMs 44..147 run 1 (slot 0).
__device__ __forceinline__ int slot_job(int bid)
{
    int s = bid % SMS, slot = bid / SMS;
    if (s < 44) return (slot < 2) ? (2 * s + slot) : -1;
    return (slot == 0) ? (88 + (s - 44)) : -1;
}

// =========================== persistent megakernel ===========================
__global__ void __launch_bounds__(NTHR, 3)
rnn_persistent(const float* __restrict__ input, const float* __restrict__ noise,
               const float* __restrict__ Wcin, const float* __restrict__ bcin,
               const float* __restrict__ W1, const float* __restrict__ b1,
               const float* __restrict__ W2, const float* __restrict__ b2,
               const float* __restrict__ W3, const float* __restrict__ b3,
               const float* __restrict__ W4, const float* __restrict__ b4,
               const float* __restrict__ Wih, const float* __restrict__ Whh,
               const float* __restrict__ bih, const float* __restrict__ bhh,
               float* __restrict__ outC, float* __restrict__ outH,
               float* __restrict__ outF)
{
    __shared__ __align__(16) float sAs[2 * SA_BUF];
    __shared__ __align__(16) float sWs[2 * SW_BUF];
    __shared__ float su[8];

    const int bid = blockIdx.x;
    const int tid = threadIdx.x;
    const int gt  = bid * NTHR + tid;

    P p { b1, b2, b3, bih, bhh };

    // -------- weight transposes (once) --------
    for (int i = gt; i < H2 * H2; i += GSTRIDE) {
        int k = i / H2, n = i % H2;
        g_W1t[i] = W1[(size_t)n * H2 + k];
        g_W2t[i] = W2[(size_t)n * H2 + k];
        g_W3t[i] = W3[(size_t)n * H2 + k];
    }
    for (int i = gt; i < HH * H3; i += GSTRIDE) {
        int k = i / H3, n = i % H3;
        g_WihT[i] = Wih[(size_t)n * HH + k];
        g_WhhT[i] = Whh[(size_t)n * HH + k];
    }
    for (int i = gt; i < II * HH; i += GSTRIDE) {
        int k = i / HH, n = i % HH;
        g_WcinT[i] = Wcin[(size_t)n * II + k];
    }
    grid_sync();

    // -------- prologue: c_in = tanh(x @ Wcin^T) -> c_concat (row = b*T+t) --------
    for (int j = bid; j < 16384; j += GRID) {
        int rt = j >> 2, ct = j & 3;
        gemm32x64<EPI_TANH, false>(input, 0, 0, II, 0, g_WcinT, HH, bcin,
                                   outC, HH, rt * 32, ct * 64, 4, sAs, sWs);
    }
    grid_sync();

    // -------- init state --------
    if (bid < BB) {
        int b = bid;
        for (int j = tid; j < HH; j += NTHR) {
            g_c[b][j] = 0.f;
            g_h[b][j] = 0.f;
            g_com[b][j] = 0.f;
            g_com[b][HH + j] = outC[(size_t)b * TT * HH + j];
        }
        if (tid == 0) g_n[b] = 0.f;
    }
    grid_sync();

    const int myjob = slot_job(bid);

    // -------- recurrent loop --------
    for (int t = 0; t < TT; t++) {
        if (myjob >= 0) exec_job(0, myjob, p, sAs, sWs);   // a1 partials + gi[0:64)
        grid_sync();
        if (myjob >= 0) exec_job(1, myjob, p, sAs, sWs);   // a2 + gi[64:96) + gh[0:32)
        grid_sync();
        if (myjob >= 0) exec_job(2, myjob, p, sAs, sWs);   // a3 + gh[32:96)
        grid_sync();

        // -------- phase U --------
        if (bid < BB) {
            int b = bid;
            float part = 0.f;
#pragma unroll
            for (int q = 0; q < 4; q++) {
                int k = tid + q * NTHR;
                float v = g_a3p[0][b][k] + g_a3p[1][b][k] + b3[k];
                part += fmaxf(v, 0.f) * W4[k];
            }
#pragma unroll
            for (int sh = 16; sh > 0; sh >>= 1)
                part += __shfl_down_sync(0xffffffffu, part, sh);
            if ((tid & 31) == 0) su[tid >> 5] = part;
            __syncthreads();
            if (tid == 0) {
                float logit = b4[0] + su[0] + su[1] + su[2] + su[3];
                float u = noise[(size_t)t * BB + b];
                float logistic = logf(u) - log1pf(-u);
                float a = sigf((logit + logistic) * 10.f);   // / TEMP
                float nold = g_n[b];
                su[4] = a;
                su[5] = nold;
                g_n[b] = nold * (1.f - a) + 1.f;
            }
            __syncthreads();
            float alpha = su[4], nold = su[5];
            float nnew = nold * (1.f - alpha) + 1.f;
#pragma unroll
            for (int u2 = 0; u2 < 2; u2++) {
                int jj = tid + u2 * NTHR;
                float c = g_c[b][jj], h = g_h[b][jj];
                float cin = outC[(size_t)b * TT * HH + (size_t)t * HH + jj];
                float r  = sigf(g_gi[b][jj] + g_gh[b][jj]);
                float z  = sigf(g_gi[b][HH + jj] + g_gh[b][HH + jj]);
                float ng = tanhf(g_gi[b][2 * HH + jj] + r * g_gh[b][2 * HH + jj]);
                float hcand = (1.f - z) * ng + z * h;
                float hnew = h * (1.f - alpha) + alpha * hcand;
                float cnew = (c * nold * (1.f - alpha) + cin) / nnew;
                g_c[b][jj] = cnew;
                g_h[b][jj] = hnew;
                outH[(size_t)b * TT * HH + (size_t)t * HH + jj] = hnew;
                g_com[b][jj] = cnew;
                if (t + 1 < TT)
                    g_com[b][HH + jj] = outC[(size_t)b * TT * HH + (size_t)(t + 1) * HH + jj];
            }
        }
        grid_sync();
    }

    // -------- epilogue: h_final = gru_cell(c_T, h_T) --------
    if (myjob >= 0) exec_job(3, myjob, p, sAs, sWs);
    grid_sync();
    if (bid < BB) {
        int b = bid;
#pragma unroll
        for (int u2 = 0; u2 < 2; u2++) {
            int jj = tid + u2 * NTHR;
            float h = g_h[b][jj];
            float r  = sigf(g_gi[b][jj] + g_gh[b][jj]);
            float z  = sigf(g_gi[b][HH + jj] + g_gh[b][HH + jj]);
            float ng = tanhf(g_gi[b][2 * HH + jj] + r * g_gh[b][2 * HH + jj]);
            outF[(size_t)b * HH + jj] = (1.f - z) * ng + z * h;
        }
    }
}

extern "C" void kernel_launch(void* const* d_in, const int* in_sizes, int n_in,
                              void* d_out, int out_size)
{
    const float* input = (const float*)d_in[0];
    const float* noise = (const float*)d_in[1];
    const float* Wcin  = (const float*)d_in[2];
    const float* bcin  = (const float*)d_in[3];
    const float* W1    = (const float*)d_in[4];
    const float* b1    = (const float*)d_in[5];
    const float* W2    = (const float*)d_in[6];
    const float* b2    = (const float*)d_in[7];
    const float* W3    = (const float*)d_in[8];
    const float* b3    = (const float*)d_in[9];
    const float* W4    = (const float*)d_in[10];
    const float* b4    = (const float*)d_in[11];
    const float* Wih   = (const float*)d_in[12];
    const float* Whh   = (const float*)d_in[13];
    const float* bih   = (const float*)d_in[14];
    const float* bhh   = (const float*)d_in[15];

    float* outC = (float*)d_out;                   // c_concat [B,T,H]
    float* outH = outC + (size_t)BB * TT * HH;     // h_concat [B,T,H]
    float* outF = outH + (size_t)BB * TT * HH;     // h_final  [B,H]

    rnn_persistent<<<GRID, NTHR>>>(input, noise, Wcin, bcin, W1, b1, W2, b2,
                                   W3, b3, W4, b4, Wih, Whh, bih, bhh,
                                   outC, outH, outF);
}

// round 9
// speedup vs baseline: 1.7318x; 1.7318x over previous
#include <cuda_runtime.h>
#include <math.h>

#define BB 256
#define TT 512
#define II 128
#define HH 256
#define H2 512
#define H3 768
#define SMS 148
#define GRID 296          // 2 CTAs per SM (classic placement: SM = LUT[bid % 148])
#define NTHR 128
#define GSTRIDE (GRID * NTHR)

typedef unsigned long long ull;

#define ASP 36            // As row pitch (floats)
#define WSP 68            // Ws row pitch (floats)
#define SA_BUF (32 * ASP)
#define SW_BUF (32 * WSP)

enum { EPI_RAW = 0, EPI_BIAS = 1, EPI_TANH = 2 };

// ---------------- persistent device scratch (no allocations) ----------------
__device__ float g_W1t[H2 * H2];     // transposed weights: Wt[k][n] = W[n][k]
__device__ float g_W2t[H2 * H2];
__device__ float g_W3t[H2 * H2];
__device__ float g_WihT[HH * H3];
__device__ float g_WhhT[HH * H3];
__device__ float g_WcinT[II * HH];

__device__ float g_com[BB][H2];      // [c | c_in_t]
__device__ float g_a1p[2][BB][H2];   // K-split partials
__device__ float g_a2p[2][BB][H2];
__device__ float g_a3p[2][BB][H2];
__device__ float g_gi[BB][H3];
__device__ float g_gh[BB][H3];
__device__ float g_c[BB][HH];
__device__ float g_h[BB][HH];
__device__ float g_n[BB];

// ---------------- hierarchical barriers ----------------
// Arrivals spread over line-strided counters (128B apart); root (bid 0) polls
// the sums and releases via a gen word. Counters/gens are monotonic and never
// reset; episode base persists across launches/graph replays via g_epoch*.
__device__ unsigned g_cntG[32 * 32];          // 32 lines for the 296-CTA barrier
__device__ unsigned g_cntL[16 * 32];          // 16 lines for the 128-CTA barrier
__device__ volatile unsigned g_genG;
__device__ volatile unsigned g_genL;
__device__ unsigned g_epochG;
__device__ unsigned g_epochL;

__device__ __forceinline__ void barrier_G(unsigned k)
{
    __syncthreads();
    if (threadIdx.x == 0) {
        __threadfence();
        atomicAdd(&g_cntG[(blockIdx.x & 31) << 5], 1u);
        if (blockIdx.x == 0) {
            unsigned long long need = (unsigned long long)k * GRID;
            for (;;) {
                unsigned long long s = 0;
#pragma unroll
                for (int i = 0; i < 32; i++)
                    s += ((volatile unsigned*)g_cntG)[i << 5];
                if (s >= need) break;
                __nanosleep(128);
            }
            __threadfence();
            g_genG = k;
        } else {
            while (g_genG < k) __nanosleep(128);
        }
        __threadfence();
    }
    __syncthreads();
}

// light barrier: only bids 0..127 participate
__device__ __forceinline__ void barrier_L(unsigned k)
{
    __syncthreads();
    if (threadIdx.x == 0) {
        __threadfence();
        atomicAdd(&g_cntL[(blockIdx.x & 15) << 5], 1u);
        if (blockIdx.x == 0) {
            unsigned long long need = (unsigned long long)k * 128u;
            for (;;) {
                unsigned long long s = 0;
#pragma unroll
                for (int i = 0; i < 16; i++)
                    s += ((volatile unsigned*)g_cntL)[i << 5];
                if (s >= need) break;
                __nanosleep(64);
            }
            __threadfence();
            g_genL = k;
        } else {
            while (g_genL < k) __nanosleep(64);
        }
        __threadfence();
    }
    __syncthreads();
}

__device__ __forceinline__ float sigf(float x) { return 1.f / (1.f + expf(-x)); }

// ---------------- packed f32x2 helpers ----------------
__device__ __forceinline__ ull pack2(float x, float y) {
    ull r; asm("mov.b64 %0,{%1,%2};" : "=l"(r) : "f"(x), "f"(y)); return r;
}
__device__ __forceinline__ void unpack2(ull v, float& x, float& y) {
    asm("mov.b64 {%0,%1},%2;" : "=f"(x), "=f"(y) : "l"(v));
}
__device__ __forceinline__ void fma2(ull& d, ull a, ull b) {
    asm("fma.rn.f32x2 %0, %1, %2, %0;" : "+l"(d) : "l"(a), "l"(b));
}

// -------------------------------------------------------------------------
// One 32x64 output tile of C = epi(A @ Wt), 128 threads, per-thread 2x8.
// (R6-proven: per kk = LDS.64 + 2xLDS.128 + 8 FFMA2)
// -------------------------------------------------------------------------
template<int EPI, bool COMBINE>
__device__ __noinline__ void gemm32x64(
    const float* __restrict__ A0, const float* __restrict__ A1,
    const float* __restrict__ Ab, int lda, int koff,
    const float* __restrict__ Wt, int ldw,
    const float* __restrict__ bias,
    float* __restrict__ C, int ldc,
    int rowBase, int colBase, int nkt,
    float* __restrict__ As, float* __restrict__ Ws)
{
    const int tid  = threadIdx.x;
    const int tx4  = (tid & 7) * 4;        // col block offset
    const int ty2  = (tid >> 3) * 2;       // row pair
    const int arow = tid >> 3;             // A-stage row (and +16)
    const int akq  = tid & 7;              // A-stage k-quad
    const int wkk  = tid >> 4;             // W-stage kk (0..7, +8,+16,+24)
    const int wc4  = (tid & 15) * 4;       // W-stage col quad

    ull c00 = 0, c01 = 0, c02 = 0, c03 = 0;
    ull c10 = 0, c11 = 0, c12 = 0, c13 = 0;
    float4 va0, va1, vw0, vw1, vw2, vw3;

#define LOAD_T(kt)                                                              \
    {                                                                           \
        int kg = koff + (kt) * 32;                                              \
        const float* ap = A0 + (size_t)(rowBase + arow) * lda + kg + akq * 4;   \
        va0 = *(const float4*)ap;                                               \
        va1 = *(const float4*)(ap + 16 * (size_t)lda);                          \
        if (COMBINE) {                                                          \
            const float* a1p = A1 + (size_t)(rowBase + arow) * lda + kg + akq * 4; \
            float4 u0 = *(const float4*)a1p;                                    \
            float4 u1 = *(const float4*)(a1p + 16 * (size_t)lda);               \
            float4 bb = *(const float4*)(Ab + kg + akq * 4);                    \
            va0.x = fmaxf(va0.x + u0.x + bb.x, 0.f);                            \
            va0.y = fmaxf(va0.y + u0.y + bb.y, 0.f);                            \
            va0.z = fmaxf(va0.z + u0.z + bb.z, 0.f);                            \
            va0.w = fmaxf(va0.w + u0.w + bb.w, 0.f);                            \
            va1.x = fmaxf(va1.x + u1.x + bb.x, 0.f);                            \
            va1.y = fmaxf(va1.y + u1.y + bb.y, 0.f);                            \
            va1.z = fmaxf(va1.z + u1.z + bb.z, 0.f);                            \
            va1.w = fmaxf(va1.w + u1.w + bb.w, 0.f);                            \
        }                                                                       \
        const float* wp = Wt + (size_t)(kg + wkk) * ldw + colBase + wc4;        \
        vw0 = *(const float4*)wp;                                               \
        vw1 = *(const float4*)(wp + 8  * (size_t)ldw);                          \
        vw2 = *(const float4*)(wp + 16 * (size_t)ldw);                          \
        vw3 = *(const float4*)(wp + 24 * (size_t)ldw);                          \
    }

#define STORE_T(bi)                                                             \
    {                                                                           \
        float* as = As + (bi) * SA_BUF;                                         \
        float* ws = Ws + (bi) * SW_BUF;                                         \
        as[(akq * 4 + 0) * ASP + arow]      = va0.x;                            \
        as[(akq * 4 + 1) * ASP + arow]      = va0.y;                            \
        as[(akq * 4 + 2) * ASP + arow]      = va0.z;                            \
        as[(akq * 4 + 3) * ASP + arow]      = va0.w;                            \
        as[(akq * 4 + 0) * ASP + arow + 16] = va1.x;                            \
        as[(akq * 4 + 1) * ASP + arow + 16] = va1.y;                            \
        as[(akq * 4 + 2) * ASP + arow + 16] = va1.z;                            \
        as[(akq * 4 + 3) * ASP + arow + 16] = va1.w;                            \
        *(float4*)(ws + (wkk + 0)  * WSP + wc4) = vw0;                          \
        *(float4*)(ws + (wkk + 8)  * WSP + wc4) = vw1;                          \
        *(float4*)(ws + (wkk + 16) * WSP + wc4) = vw2;                          \
        *(float4*)(ws + (wkk + 24) * WSP + wc4) = vw3;                          \
    }

    LOAD_T(0);
    STORE_T(0);
    __syncthreads();

    for (int kt = 0; kt < nkt; kt++) {
        if (kt + 1 < nkt) LOAD_T(kt + 1);
        {
            const float* as = As + (kt & 1) * SA_BUF;
            const float* ws = Ws + (kt & 1) * SW_BUF;
#pragma unroll
            for (int kk = 0; kk < 32; kk++) {
                ull a01 = *(const ull*)(as + kk * ASP + ty2);
                float a0, a1;
                unpack2(a01, a0, a1);
                ull d0 = pack2(a0, a0);
                ull d1 = pack2(a1, a1);
                ulonglong2 wA = *(const ulonglong2*)(ws + kk * WSP + tx4);
                ulonglong2 wB = *(const ulonglong2*)(ws + kk * WSP + 32 + tx4);
                fma2(c00, d0, wA.x);
                fma2(c01, d0, wA.y);
                fma2(c02, d0, wB.x);
                fma2(c03, d0, wB.y);
                fma2(c10, d1, wA.x);
                fma2(c11, d1, wA.y);
                fma2(c12, d1, wB.x);
                fma2(c13, d1, wB.y);
            }
        }
        if (kt + 1 < nkt) STORE_T((kt + 1) & 1);
        __syncthreads();
    }
#undef LOAD_T
#undef STORE_T

    float4 o00, o01, o10, o11;
    unpack2(c00, o00.x, o00.y); unpack2(c01, o00.z, o00.w);
    unpack2(c02, o01.x, o01.y); unpack2(c03, o01.z, o01.w);
    unpack2(c10, o10.x, o10.y); unpack2(c11, o10.z, o10.w);
    unpack2(c12, o11.x, o11.y); unpack2(c13, o11.z, o11.w);
    if (EPI != EPI_RAW) {
        float4 b0 = *(const float4*)(bias + colBase + tx4);
        float4 b1 = *(const float4*)(bias + colBase + 32 + tx4);
        o00.x += b0.x; o00.y += b0.y; o00.z += b0.z; o00.w += b0.w;
        o10.x += b0.x; o10.y += b0.y; o10.z += b0.z; o10.w += b0.w;
        o01.x += b1.x; o01.y += b1.y; o01.z += b1.z; o01.w += b1.w;
        o11.x += b1.x; o11.y += b1.y; o11.z += b1.z; o11.w += b1.w;
        if (EPI == EPI_TANH) {
            o00.x = tanhf(o00.x); o00.y = tanhf(o00.y); o00.z = tanhf(o00.z); o00.w = tanhf(o00.w);
            o01.x = tanhf(o01.x); o01.y = tanhf(o01.y); o01.z = tanhf(o01.z); o01.w = tanhf(o01.w);
            o10.x = tanhf(o10.x); o10.y = tanhf(o10.y); o10.z = tanhf(o10.z); o10.w = tanhf(o10.w);
            o11.x = tanhf(o11.x); o11.y = tanhf(o11.y); o11.z = tanhf(o11.z); o11.w = tanhf(o11.w);
        }
    }
    float* crow0 = C + (size_t)(rowBase + ty2) * ldc + colBase;
    float* crow1 = crow0 + ldc;
    *(float4*)(crow0 + tx4)      = o00;
    *(float4*)(crow0 + 32 + tx4) = o01;
    *(float4*)(crow1 + tx4)      = o10;
    *(float4*)(crow1 + 32 + tx4) = o11;
}

struct P {
    const float *b1, *b2, *b3, *bih, *bhh;
};

// gate jobs: gq in [0,192): gq<96 -> gi tile, else gh tile (rt x ct of 8x12)
__device__ __forceinline__ void do_g(int gq, const P& p, float* As, float* Ws)
{
    bool is_gi = gq < 96;
    int q = is_gi ? gq : gq - 96;
    int rt = q / 12, ct = q % 12;
    if (is_gi)
        gemm32x64<EPI_BIAS, false>(&g_c[0][0], 0, 0, HH, 0, g_WihT, H3, p.bih,
                                   &g_gi[0][0], H3, rt * 32, ct * 64, 8, As, Ws);
    else
        gemm32x64<EPI_BIAS, false>(&g_h[0][0], 0, 0, HH, 0, g_WhhT, H3, p.bhh,
                                   &g_gh[0][0], H3, rt * 32, ct * 64, 8, As, Ws);
}

// MLP job (one per slot-0 CTA per phase): j in [0,128)
__device__ __forceinline__ void do_a(int ph, int j, const P& p, float* As, float* Ws)
{
    int rt = j >> 4, kh = (j >> 3) & 1, ct = j & 7;
    int rb = rt * 32, cb = ct * 64, ko = kh * 256;
    if (ph == 0)
        gemm32x64<EPI_RAW, false>(&g_com[0][0], 0, 0, H2, ko, g_W1t, H2, 0,
                                  &g_a1p[kh][0][0], H2, rb, cb, 8, As, Ws);
    else if (ph == 1)
        gemm32x64<EPI_RAW, true>(&g_a1p[0][0][0], &g_a1p[1][0][0], p.b1, H2, ko,
                                 g_W2t, H2, 0, &g_a2p[kh][0][0], H2, rb, cb, 8, As, Ws);
    else
        gemm32x64<EPI_RAW, true>(&g_a2p[0][0][0], &g_a2p[1][0][0], p.b2, H2, ko,
                                 g_W3t, H2, 0, &g_a3p[kh][0][0], H2, rb, cb, 8, As, Ws);
}

// =========================== persistent megakernel ===========================
__global__ void __launch_bounds__(NTHR)
rnn_persistent(const float* __restrict__ input, const float* __restrict__ noise,
               const float* __restrict__ Wcin, const float* __restrict__ bcin,
               const float* __restrict__ W1, const float* __restrict__ b1,
               const float* __restrict__ W2, const float* __restrict__ b2,
               const float* __restrict__ W3, const float* __restrict__ b3,
               const float* __restrict__ W4, const float* __restrict__ b4,
               const float* __restrict__ Wih, const float* __restrict__ Whh,
               const float* __restrict__ bih, const float* __restrict__ bhh,
               float* __restrict__ outC, float* __restrict__ outH,
               float* __restrict__ outF)
{
    __shared__ __align__(16) float sAs[2 * SA_BUF];
    __shared__ __align__(16) float sWs[2 * SW_BUF];
    __shared__ float su[8];

    const int bid = blockIdx.x;
    const int tid = threadIdx.x;
    const int gt  = bid * NTHR + tid;

    unsigned kG = g_epochG;     // episode bases persist across launches/replays
    unsigned kL = g_epochL;

    P p { b1, b2, b3, bih, bhh };

    // -------- weight transposes (once per launch) --------
    for (int i = gt; i < H2 * H2; i += GSTRIDE) {
        int k = i / H2, n = i % H2;
        g_W1t[i] = W1[(size_t)n * H2 + k];
        g_W2t[i] = W2[(size_t)n * H2 + k];
        g_W3t[i] = W3[(size_t)n * H2 + k];
    }
    for (int i = gt; i < HH * H3; i += GSTRIDE) {
        int k = i / H3, n = i % H3;
        g_WihT[i] = Wih[(size_t)n * HH + k];
        g_WhhT[i] = Whh[(size_t)n * HH + k];
    }
    for (int i = gt; i < II * HH; i += GSTRIDE) {
        int k = i / HH, n = i % HH;
        g_WcinT[i] = Wcin[(size_t)n * II + k];
    }
    barrier_G(++kG);

    // -------- prologue: c_in = tanh(x @ Wcin^T) -> c_concat (row = b*T+t) --------
    for (int j = bid; j < 16384; j += GRID) {
        int rt = j >> 2, ct = j & 3;
        gemm32x64<EPI_TANH, false>(input, 0, 0, II, 0, g_WcinT, HH, bcin,
                                   outC, HH, rt * 32, ct * 64, 4, sAs, sWs);
    }
    barrier_G(++kG);

    // -------- init state --------
    if (bid < BB) {
        int b = bid;
        for (int j = tid; j < HH; j += NTHR) {
            g_c[b][j] = 0.f;
            g_h[b][j] = 0.f;
            g_com[b][j] = 0.f;
            g_com[b][HH + j] = outC[(size_t)b * TT * HH + j];
        }
        if (tid == 0) g_n[b] = 0.f;
    }
    barrier_G(++kG);

    // -------- recurrent loop --------
    for (int t = 0; t < TT; t++) {
        if (bid < 128) {
            // slot-0: MLP chain with light (128-CTA) barriers
            do_a(0, bid, p, sAs, sWs);
            barrier_L(++kL);
            do_a(1, bid, p, sAs, sWs);
            barrier_L(++kL);
            do_a(2, bid, p, sAs, sWs);
        } else {
            // gate workers: gi/gh depend only on U(t-1); run in the MLP's slack
            kL += 2;                         // keep episode count uniform
            int j = bid - 128;               // 0..167
            do_g(j, p, sAs, sWs);
            if (j < 24) do_g(168 + j, p, sAs, sWs);
        }
        barrier_G(++kG);                     // a3 + gates all done

        // -------- phase U --------
        if (bid < BB) {
            int b = bid;
            float part = 0.f;
#pragma unroll
            for (int q = 0; q < 4; q++) {
                int k = tid + q * NTHR;
                float v = g_a3p[0][b][k] + g_a3p[1][b][k] + b3[k];
                part += fmaxf(v, 0.f) * W4[k];
            }
#pragma unroll
            for (int sh = 16; sh > 0; sh >>= 1)
                part += __shfl_down_sync(0xffffffffu, part, sh);
            if ((tid & 31) == 0) su[tid >> 5] = part;
            __syncthreads();
            if (tid == 0) {
                float logit = b4[0] + su[0] + su[1] + su[2] + su[3];
                float u = noise[(size_t)t * BB + b];
                float logistic = logf(u) - log1pf(-u);
                float a = sigf((logit + logistic) * 10.f);   // / TEMP
                float nold = g_n[b];
                su[4] = a;
                su[5] = nold;
                g_n[b] = nold * (1.f - a) + 1.f;
            }
            __syncthreads();
            float alpha = su[4], nold = su[5];
            float nnew = nold * (1.f - alpha) + 1.f;
#pragma unroll
            for (int u2 = 0; u2 < 2; u2++) {
                int jj = tid + u2 * NTHR;
                float c = g_c[b][jj], h = g_h[b][jj];
                float cin = outC[(size_t)b * TT * HH + (size_t)t * HH + jj];
                float r  = sigf(g_gi[b][jj] + g_gh[b][jj]);
                float z  = sigf(g_gi[b][HH + jj] + g_gh[b][HH + jj]);
                float ng = tanhf(g_gi[b][2 * HH + jj] + r * g_gh[b][2 * HH + jj]);
                float hcand = (1.f - z) * ng + z * h;
                float hnew = h * (1.f - alpha) + alpha * hcand;
                float cnew = (c * nold * (1.f - alpha) + cin) / nnew;
                g_c[b][jj] = cnew;
                g_h[b][jj] = hnew;
                outH[(size_t)b * TT * HH + (size_t)t * HH + jj] = hnew;
                g_com[b][jj] = cnew;
                if (t + 1 < TT)
                    g_com[b][HH + jj] = outC[(size_t)b * TT * HH + (size_t)(t + 1) * HH + jj];
            }
        }
        barrier_G(++kG);                     // U done -> next step may start
    }

    // -------- epilogue: h_final = gru_cell(c_T, h_T) --------
    if (bid < 192) do_g(bid, p, sAs, sWs);
    barrier_G(++kG);
    if (bid < BB) {
        int b = bid;
#pragma unroll
        for (int u2 = 0; u2 < 2; u2++) {
            int jj = tid + u2 * NTHR;
            float h = g_h[b][jj];
            float r  = sigf(g_gi[b][jj] + g_gh[b][jj]);
            float z  = sigf(g_gi[b][HH + jj] + g_gh[b][HH + jj]);
            float ng = tanhf(g_gi[b][2 * HH + jj] + r * g_gh[b][2 * HH + jj]);
            outF[(size_t)b * HH + jj] = (1.f - z) * ng + z * h;
        }
    }

    // persist episode bases for the next launch / graph replay
    if (bid == 0 && tid == 0) {
        g_epochG = kG;
        g_epochL = kL;
    }
}

extern "C" void kernel_launch(void* const* d_in, const int* in_sizes, int n_in,
                              void* d_out, int out_size)
{
    const float* input = (const float*)d_in[0];
    const float* noise = (const float*)d_in[1];
    const float* Wcin  = (const float*)d_in[2];
    const float* bcin  = (const float*)d_in[3];
    const float* W1    = (const float*)d_in[4];
    const float* b1    = (const float*)d_in[5];
    const float* W2    = (const float*)d_in[6];
    const float* b2    = (const float*)d_in[7];
    const float* W3    = (const float*)d_in[8];
    const float* b3    = (const float*)d_in[9];
    const float* W4    = (const float*)d_in[10];
    const float* b4    = (const float*)d_in[11];
    const float* Wih   = (const float*)d_in[12];
    const float* Whh   = (const float*)d_in[13];
    const float* bih   = (const float*)d_in[14];
    const float* bhh   = (const float*)d_in[15];

    float* outC = (float*)d_out;                   // c_concat [B,T,H]
    float* outH = outC + (size_t)BB * TT * HH;     // h_concat [B,T,H]
    float* outF = outH + (size_t)BB * TT * HH;     // h_final  [B,H]

    rnn_persistent<<<GRID, NTHR>>>(input, noise, Wcin, bcin, W1, b1, W2, b2,
                                   W3, b3, W4, b4, Wih, Whh, bih, bhh,
                                   outC, outH, outF);
}